// round 16
// baseline (speedup 1.0000x reference)
#include <cuda_runtime.h>
#include <cuda_fp16.h>
#include <cstdint>

#define N_NODES 100000
#define N_EDGES 1600000
#define N_HOPS 3
#define D_FEAT 128
#define D_HID 256
#define NUM_GRAPHS 64
#define TM 128
#define NT_TILES ((N_NODES + TM - 1) / TM)   // 782
#define GRID_F 148
#define THREADS_F 512

// ---- fused smem layout (bytes) ----
#define OFF_B1 0                      // 1024 (b1 fp32)
#define OFF_X0 1024                   // 32768: X fp16 buf0
#define OFF_X1 (OFF_X0 + 32768)       // 32768: X fp16 buf1
#define OFF_R  (OFF_X1 + 32768)       // 65536: R fp16 [128][256] as 2 images
#define OFF_W  (OFF_R + 65536)        // 65536: W fp16 [half][k128][n128]
#define OFF_C0 (OFF_W + 65536)        // 16384: C' buf0
#define OFF_C1 (OFF_C0 + 16384)       // 16384: C' buf1
#define SMEM_F (OFF_C1 + 16384)       // 230400

// Scratch (device globals; no runtime allocation allowed)
__device__ __align__(16) float g_C[(size_t)N_NODES * NUM_GRAPHS];  // 25.6 MB
__device__ __align__(16) float g_CR[NUM_GRAPHS * D_HID];
__device__ float g_rowsum[NUM_GRAPHS];
__device__ int g_idx64;
__device__ unsigned char g_b8[N_NODES];
__device__ __align__(16) unsigned char g_W1img[65536];                   // W1 fp16 swizzled
__device__ __align__(16) unsigned char g_X16[(size_t)NT_TILES * 32768];  // X fp16 tiles

// ---------------- helpers ----------------
__device__ __forceinline__ uint32_t smem_u32(const void* p) {
    uint32_t a;
    asm("{ .reg .u64 t; cvta.to.shared.u64 t, %1; cvt.u32.u64 %0, t; }" : "=r"(a) : "l"(p));
    return a;
}
__device__ __forceinline__ uint32_t swz(uint32_t r, uint32_t cb) {
    return r * 256u + (((cb) & ~15u) ^ ((r & 7u) << 4)) + (cb & 15u);
}
__device__ __forceinline__ void ldsm4(uint32_t* r, uint32_t addr) {
    asm volatile("ldmatrix.sync.aligned.m8n8.x4.shared.b16 {%0,%1,%2,%3}, [%4];"
                 : "=r"(r[0]), "=r"(r[1]), "=r"(r[2]), "=r"(r[3]) : "r"(addr));
}
__device__ __forceinline__ void ldsm4t(uint32_t* r, uint32_t addr) {
    asm volatile("ldmatrix.sync.aligned.m8n8.x4.trans.shared.b16 {%0,%1,%2,%3}, [%4];"
                 : "=r"(r[0]), "=r"(r[1]), "=r"(r[2]), "=r"(r[3]) : "r"(addr));
}
__device__ __forceinline__ void mma_fp16(float* c, const uint32_t* a, const uint32_t* b) {
    asm volatile("mma.sync.aligned.m16n8k16.row.col.f32.f16.f16.f32 "
                 "{%0,%1,%2,%3}, {%4,%5,%6,%7}, {%8,%9}, {%0,%1,%2,%3};"
                 : "+f"(c[0]), "+f"(c[1]), "+f"(c[2]), "+f"(c[3])
                 : "r"(a[0]), "r"(a[1]), "r"(a[2]), "r"(a[3]), "r"(b[0]), "r"(b[1]));
}
__device__ __forceinline__ uint32_t pkhf2(float a, float b) {
    __half2 t = __floats2half2_rn(a, b);
    return *reinterpret_cast<uint32_t*>(&t);
}
__device__ __forceinline__ void cp16(uint32_t dst, const void* src) {
    asm volatile("cp.async.cg.shared.global [%0], [%1], 16;" :: "r"(dst), "l"(src));
}
#define CP_COMMIT() asm volatile("cp.async.commit_group;" ::: "memory")
#define CP_WAIT0() asm volatile("cp.async.wait_group 0;" ::: "memory")
__device__ __forceinline__ int load_index(const void* p, long long i, int is64) {
    if (is64) return (int)((const long long*)p)[i];
    return ((const int*)p)[i];
}

// ---------- detect int width + zero accumulators ----------
__global__ void k_detect(const unsigned int* __restrict__ ei_words) {
    int t = threadIdx.x;
    if (t == 0) {
        unsigned int acc = 0;
#pragma unroll
        for (int i = 0; i < 64; i++) acc |= ei_words[2 * i + 1];
        g_idx64 = (acc == 0u) ? 1 : 0;
    }
    for (int i = t; i < NUM_GRAPHS * D_HID; i += 256) g_CR[i] = 0.f;
    if (t < NUM_GRAPHS) g_rowsum[t] = 0.f;
}

// ---------- batch -> uint8 + rowsum pw0 part ----------
__global__ void k_prep(const void* __restrict__ batch, const float* __restrict__ prop_w) {
    __shared__ float h[NUM_GRAPHS];
    int t = threadIdx.x;
    if (t < NUM_GRAPHS) h[t] = 0.f;
    __syncthreads();
    int is64 = g_idx64;
    float pw0 = prop_w[0];
    int i = blockIdx.x * blockDim.x + t;
    if (i < N_NODES) {
        int g = load_index(batch, i, is64) & (NUM_GRAPHS - 1);
        g_b8[i] = (unsigned char)g;
        atomicAdd(&h[g], pw0);
    }
    __syncthreads();
    if (t < NUM_GRAPHS && h[t] != 0.f) atomicAdd(&g_rowsum[t], h[t]);
}

// ---------- W1 -> pre-swizzled fp16 image ----------
__global__ void k_prepW(const float* __restrict__ w1) {
    int idx = blockIdx.x * blockDim.x + threadIdx.x;
    if (idx >= 2 * 128 * 128) return;
    int half = idx >> 14;
    int k = (idx >> 7) & 127;
    int n = idx & 127;
    float v = w1[(size_t)k * D_HID + half * 128 + n];
    uint32_t off = swz((uint32_t)k, (uint32_t)n * 2);
    *reinterpret_cast<__half*>(g_W1img + half * 32768 + off) = __float2half_rn(v);
}

// ---------- X -> fp16 pre-swizzled per-tile chunks ----------
__global__ void k_prepX(const float* __restrict__ x) {
    int tile = blockIdx.x;
    int t = threadIdx.x;  // 256
    int row = t >> 1;
    int c0 = (t & 1) * 64;
    int node = tile * TM + row;
    bool valid = node < N_NODES;
    const float* xr = x + (size_t)node * D_FEAT + c0;
    unsigned char* dst = g_X16 + (size_t)tile * 32768;
#pragma unroll
    for (int i = 0; i < 16; i++) {
        float4 f = valid ? *reinterpret_cast<const float4*>(xr + i * 4)
                         : make_float4(0.f, 0.f, 0.f, 0.f);
        uint2 hv = make_uint2(pkhf2(f.x, f.y), pkhf2(f.z, f.w));
        *reinterpret_cast<uint2*>(dst + swz((uint32_t)row, (uint32_t)(c0 + i * 4) * 2)) = hv;
    }
}

// ---------- zero C ----------
__global__ void k_zeroC() {
    size_t i = (size_t)blockIdx.x * blockDim.x + threadIdx.x;
    size_t stride = (size_t)gridDim.x * blockDim.x;
    float4 z = make_float4(0.f, 0.f, 0.f, 0.f);
    size_t n4 = (size_t)N_NODES * NUM_GRAPHS / 4;
    for (size_t j = i; j < n4; j += stride) reinterpret_cast<float4*>(g_C)[j] = z;
}

// ---------- edge scatter into C + rowsum edge part ----------
__global__ void k_edges(const void* __restrict__ ei, const float* __restrict__ ew,
                        const float* __restrict__ prop_w) {
    __shared__ float h[NUM_GRAPHS];
    int t = threadIdx.x;
    if (t < NUM_GRAPHS) h[t] = 0.f;
    __syncthreads();
    float pw0 = prop_w[1], pw1 = prop_w[2], pw2 = prop_w[3];
    int is64 = g_idx64;
    const long long total = (long long)N_HOPS * N_EDGES;
    long long stride = (long long)gridDim.x * blockDim.x;
    for (long long idx = (long long)blockIdx.x * blockDim.x + t; idx < total;
         idx += stride) {
        int hop = (int)(idx / N_EDGES);
        long long r = idx - (long long)hop * N_EDGES;
        long long base = (long long)hop * 2 * N_EDGES;
        int s = load_index(ei, base + r, is64);
        int d = load_index(ei, base + N_EDGES + r, is64);
        s = min(max(s, 0), N_NODES - 1);
        d = min(max(d, 0), N_NODES - 1);
        float w = ew[(size_t)hop * N_EDGES + r];
        float pw = (hop == 0) ? pw0 : (hop == 1) ? pw1 : pw2;
        int g = g_b8[d];
        float val = pw * w;
        atomicAdd(&g_C[(size_t)s * NUM_GRAPHS + g], val);
        atomicAdd(&h[g], val);
    }
    __syncthreads();
    if (t < NUM_GRAPHS && h[t] != 0.f) atomicAdd(&g_rowsum[t], h[t]);
}

// ---------- fused: cp.async X + double-buffered C, 2 syncs/tile ----------
__global__ void __launch_bounds__(THREADS_F, 1)
k_fused(const float* __restrict__ b1, const float* __restrict__ prop_w) {
    extern __shared__ char sm[];
    const uint32_t smb = smem_u32(sm);
    float* sb1 = reinterpret_cast<float*>(sm + OFF_B1);

    const int t = threadIdx.x;
    const int lane = t & 31;
    const int w = t >> 5;
    const float pw0 = prop_w[0];

    if (t < 256) sb1[t] = b1[t];
    {
        const uint4* src = reinterpret_cast<const uint4*>(g_W1img);
        uint4* dst = reinterpret_cast<uint4*>(sm + OFF_W);
#pragma unroll
        for (int i = 0; i < 8; i++) dst[t + i * THREADS_F] = src[t + i * THREADS_F];
    }

    const int m1base = (w & 3) * 32;
    const int hsel1 = w >> 3;
    const int n1base = ((w >> 2) & 1) * 64;
    const int m2base = (w & 3) * 16;
    const int hsel2 = w >> 3;
    const int n2base = ((w >> 2) & 1) * 64;

    const uint32_t lr = lane & 15;
    const uint32_t lc = (lane >> 4) * 16;
    const int qrow = lane >> 2;
    const int qcol = (lane & 3) * 2;

    float accG[8][4];
#pragma unroll
    for (int b = 0; b < 8; b++)
#pragma unroll
        for (int c = 0; c < 4; c++) accG[b][c] = 0.f;

    // ---- prologue: cp.async X(tile0) -> X0, stage C(tile0) -> C0 ----
    int buf = 0;
    {
        int tile = blockIdx.x;
        const char* xs = (const char*)g_X16 + (size_t)tile * 32768 + t * 16;
        uint32_t xd = smb + OFF_X0 + t * 16;
#pragma unroll
        for (int i = 0; i < 4; i++) cp16(xd + i * 8192, xs + i * 8192);
        CP_COMMIT();

        int node = t >> 2;
        int g0 = (t & 3) * 16;
        int gn = tile * TM + node;
        bool valid = gn < N_NODES;
        int gb = valid ? (int)g_b8[gn] : -1;
        const float* cr = g_C + (size_t)gn * NUM_GRAPHS + g0;
#pragma unroll
        for (int i = 0; i < 4; i++) {
            float4 f = valid ? *reinterpret_cast<const float4*>(cr + i * 4)
                             : make_float4(0.f, 0.f, 0.f, 0.f);
#pragma unroll
            for (int j = 0; j < 4; j++) {
                int g = g0 + i * 4 + j;
                float v = ((const float*)&f)[j];
                if (g == gb) v += pw0;
                *reinterpret_cast<__half*>(sm + OFF_C0 + swz((uint32_t)g, (uint32_t)node * 2)) =
                    __float2half_rn(v);
            }
        }
    }

    for (int tile = blockIdx.x; tile < NT_TILES; tile += gridDim.x) {
        CP_WAIT0();
        __syncthreads();  // X[cur]+C[cur] ready; all prev-tile readers done

        const uint32_t Xb = smb + (buf ? OFF_X1 : OFF_X0);
        const uint32_t Cb = smb + (buf ? OFF_C1 : OFF_C0);

        // ---- prefetch next tile: C' stage (overlaps GEMM1 latency) + cp.async X ----
        int next = tile + gridDim.x;
        if (next < NT_TILES) {
            const char* xs = (const char*)g_X16 + (size_t)next * 32768 + t * 16;
            uint32_t xd = smb + (buf ? OFF_X0 : OFF_X1) + t * 16;
#pragma unroll
            for (int i = 0; i < 4; i++) cp16(xd + i * 8192, xs + i * 8192);

            char* cdst = sm + (buf ? OFF_C0 : OFF_C1);
            int node = t >> 2;
            int g0 = (t & 3) * 16;
            int gn = next * TM + node;
            bool valid = gn < N_NODES;
            int gb = valid ? (int)g_b8[gn] : -1;
            const float* cr = g_C + (size_t)gn * NUM_GRAPHS + g0;
#pragma unroll
            for (int i = 0; i < 4; i++) {
                float4 f = valid ? *reinterpret_cast<const float4*>(cr + i * 4)
                                 : make_float4(0.f, 0.f, 0.f, 0.f);
#pragma unroll
                for (int j = 0; j < 4; j++) {
                    int g = g0 + i * 4 + j;
                    float v = ((const float*)&f)[j];
                    if (g == gb) v += pw0;
                    *reinterpret_cast<__half*>(cdst + swz((uint32_t)g, (uint32_t)node * 2)) =
                        __float2half_rn(v);
                }
            }
        }
        CP_COMMIT();

        // ---- GEMM1: acc1[m32][n64] = X @ W ----
        float acc1[2][8][4];
#pragma unroll
        for (int a = 0; a < 2; a++)
#pragma unroll
            for (int b = 0; b < 8; b++)
#pragma unroll
                for (int c = 0; c < 4; c++) acc1[a][b][c] = 0.f;
        {
            uint32_t Bb = smb + OFF_W + hsel1 * 32768;
#pragma unroll
            for (int k0 = 0; k0 < 128; k0 += 16) {
                uint32_t a[2][4], b[4][4];
#pragma unroll
                for (int mg = 0; mg < 2; mg++)
                    ldsm4(a[mg], Xb + swz(m1base + mg * 16 + lr, k0 * 2 + lc));
#pragma unroll
                for (int nt2 = 0; nt2 < 4; nt2++)
                    ldsm4t(b[nt2], Bb + swz(k0 + lr, (n1base + nt2 * 16) * 2 + lc));
#pragma unroll
                for (int mg = 0; mg < 2; mg++)
#pragma unroll
                    for (int nt = 0; nt < 8; nt++)
                        mma_fp16(acc1[mg][nt], a[mg], &b[nt >> 1][(nt & 1) * 2]);
            }
        }
        // ---- bias + relu -> R ----
        {
            char* Rimg = sm + OFF_R + hsel1 * 32768;
#pragma unroll
            for (int mg = 0; mg < 2; mg++) {
                int row0 = m1base + mg * 16 + qrow;
#pragma unroll
                for (int nt = 0; nt < 8; nt++) {
                    int col = n1base + nt * 8 + qcol;
                    float b0 = sb1[hsel1 * 128 + col];
                    float b1v = sb1[hsel1 * 128 + col + 1];
#pragma unroll
                    for (int rh = 0; rh < 2; rh++) {
                        float v0 = fmaxf(acc1[mg][nt][rh * 2 + 0] + b0, 0.f);
                        float v1 = fmaxf(acc1[mg][nt][rh * 2 + 1] + b1v, 0.f);
                        *reinterpret_cast<uint32_t*>(
                            Rimg + swz((uint32_t)(row0 + rh * 8), (uint32_t)col * 2)) =
                            pkhf2(v0, v1);
                    }
                }
            }
        }
        __syncthreads();  // R ready

        // ---- GEMM2: accG += C'[64 x 128] @ R[128 x 256] ----
        {
            uint32_t Bb = smb + OFF_R + hsel2 * 32768;
#pragma unroll
            for (int k0 = 0; k0 < 128; k0 += 16) {
                uint32_t a[4], b[4][4];
                ldsm4(a, Cb + swz(m2base + lr, k0 * 2 + lc));
#pragma unroll
                for (int nt2 = 0; nt2 < 4; nt2++)
                    ldsm4t(b[nt2], Bb + swz(k0 + lr, (n2base + nt2 * 16) * 2 + lc));
#pragma unroll
                for (int nt = 0; nt < 8; nt++)
                    mma_fp16(accG[nt], a, &b[nt >> 1][(nt & 1) * 2]);
            }
        }
        buf ^= 1;
    }

    // ---- drain persistent accumulators ----
#pragma unroll
    for (int nt = 0; nt < 8; nt++) {
        int gr = m2base + qrow;
        int col = hsel2 * 128 + n2base + nt * 8 + qcol;
        atomicAdd(&g_CR[gr * D_HID + col], accG[nt][0]);
        atomicAdd(&g_CR[gr * D_HID + col + 1], accG[nt][1]);
        atomicAdd(&g_CR[(gr + 8) * D_HID + col], accG[nt][2]);
        atomicAdd(&g_CR[(gr + 8) * D_HID + col + 1], accG[nt][3]);
    }
}

// ---------- final: pooled = CR @ w2 + rowsum*b2, log_softmax ----------
__global__ void k_final(const float* __restrict__ w2, const float* __restrict__ b2,
                        float* __restrict__ out) {
    int g = blockIdx.x;
    int f = threadIdx.x;
    float v = g_rowsum[g] * b2[f];
    const float* cr = g_CR + g * D_HID;
#pragma unroll 8
    for (int k = 0; k < D_HID; k++) v += cr[k] * w2[k * D_FEAT + f];

    __shared__ float sh[D_FEAT];
    sh[f] = v;
    __syncthreads();
    for (int s = D_FEAT / 2; s > 0; s >>= 1) {
        if (f < s) sh[f] = fmaxf(sh[f], sh[f + s]);
        __syncthreads();
    }
    float m = sh[0];
    __syncthreads();
    sh[f] = expf(v - m);
    __syncthreads();
    for (int s = D_FEAT / 2; s > 0; s >>= 1) {
        if (f < s) sh[f] += sh[f + s];
        __syncthreads();
    }
    float lse = logf(sh[0]);
    out[g * D_FEAT + f] = v - m - lse;
}

extern "C" void kernel_launch(void* const* d_in, const int* in_sizes, int n_in,
                              void* d_out, int out_size) {
    const float* x = (const float*)d_in[0];
    const void* ei = d_in[1];
    const float* ew = (const float*)d_in[2];
    const void* batch = d_in[3];
    const float* w1 = (const float*)d_in[4];
    const float* b1 = (const float*)d_in[5];
    const float* w2 = (const float*)d_in[6];
    const float* b2 = (const float*)d_in[7];
    const float* pw = (const float*)d_in[8];
    float* out = (float*)d_out;

    cudaFuncSetAttribute(k_fused, cudaFuncAttributeMaxDynamicSharedMemorySize, SMEM_F);

    cudaStream_t s2;
    cudaStreamCreateWithFlags(&s2, cudaStreamNonBlocking);
    cudaEvent_t eFork, eJoin;
    cudaEventCreateWithFlags(&eFork, cudaEventDisableTiming);
    cudaEventCreateWithFlags(&eJoin, cudaEventDisableTiming);

    // fork: W/X fp16 conversion (independent of edges chain, hidden under it)
    cudaEventRecord(eFork, 0);
    cudaStreamWaitEvent(s2, eFork, 0);
    k_prepW<<<128, 256, 0, s2>>>(w1);
    k_prepX<<<NT_TILES, 256, 0, s2>>>(x);
    cudaEventRecord(eJoin, s2);

    // main chain: build C
    k_detect<<<1, 256>>>((const unsigned int*)ei);
    k_prep<<<(N_NODES + 255) / 256, 256>>>(batch, pw);
    k_zeroC<<<2048, 256>>>();
    k_edges<<<4096, 256>>>(ei, ew, pw);

    cudaStreamWaitEvent(0, eJoin, 0);
    k_fused<<<GRID_F, THREADS_F, SMEM_F>>>(b1, pw);
    k_final<<<NUM_GRAPHS, D_FEAT>>>(w2, b2, out);
}

// round 17
// speedup vs baseline: 1.1341x; 1.1341x over previous
#include <cuda_runtime.h>
#include <cuda_fp16.h>
#include <cstdint>

#define N_NODES 100000
#define N_EDGES 1600000
#define N_HOPS 3
#define D_FEAT 128
#define D_HID 256
#define NUM_GRAPHS 64
#define TM 128
#define NT_TILES ((N_NODES + TM - 1) / TM)   // 782
#define GRID_F 148
#define THREADS_F 512

// ---- fused smem layout (bytes) ----
#define OFF_B1 0                      // 1024 (b1 fp32)
#define OFF_X  1024                   // 32768: X fp16 [128][128] swizzled
#define OFF_R  (OFF_X + 32768)        // 65536: R fp16 [128][256] as 2 swizzle images
#define OFF_W  (OFF_R + 65536)        // 65536: W fp16 [half][k128][n128]
#define OFF_C  (OFF_W + 65536)        // 16384: C' fp16 [64][128] swizzled
#define SMEM_F (OFF_C + 16384)        // 181248

// Scratch (device globals; no runtime allocation allowed)
__device__ __align__(16) float g_C[(size_t)N_NODES * NUM_GRAPHS];  // 25.6 MB
__device__ __align__(16) float g_CR[NUM_GRAPHS * D_HID];
__device__ float g_rowsum[NUM_GRAPHS];
__device__ int g_idx64;
__device__ unsigned char g_b8[N_NODES];
__device__ __align__(16) unsigned char g_W1img[65536];  // W1 fp16 pre-swizzled

// ---------------- helpers ----------------
__device__ __forceinline__ uint32_t smem_u32(const void* p) {
    uint32_t a;
    asm("{ .reg .u64 t; cvta.to.shared.u64 t, %1; cvt.u32.u64 %0, t; }" : "=r"(a) : "l"(p));
    return a;
}
__device__ __forceinline__ uint32_t swz(uint32_t r, uint32_t cb) {
    return r * 256u + (((cb) & ~15u) ^ ((r & 7u) << 4)) + (cb & 15u);
}
__device__ __forceinline__ void ldsm4(uint32_t* r, uint32_t addr) {
    asm volatile("ldmatrix.sync.aligned.m8n8.x4.shared.b16 {%0,%1,%2,%3}, [%4];"
                 : "=r"(r[0]), "=r"(r[1]), "=r"(r[2]), "=r"(r[3]) : "r"(addr));
}
__device__ __forceinline__ void ldsm4t(uint32_t* r, uint32_t addr) {
    asm volatile("ldmatrix.sync.aligned.m8n8.x4.trans.shared.b16 {%0,%1,%2,%3}, [%4];"
                 : "=r"(r[0]), "=r"(r[1]), "=r"(r[2]), "=r"(r[3]) : "r"(addr));
}
__device__ __forceinline__ void mma_fp16(float* c, const uint32_t* a, const uint32_t* b) {
    asm volatile("mma.sync.aligned.m16n8k16.row.col.f32.f16.f16.f32 "
                 "{%0,%1,%2,%3}, {%4,%5,%6,%7}, {%8,%9}, {%0,%1,%2,%3};"
                 : "+f"(c[0]), "+f"(c[1]), "+f"(c[2]), "+f"(c[3])
                 : "r"(a[0]), "r"(a[1]), "r"(a[2]), "r"(a[3]), "r"(b[0]), "r"(b[1]));
}
__device__ __forceinline__ uint32_t pkhf2(float a, float b) {
    __half2 t = __floats2half2_rn(a, b);
    return *reinterpret_cast<uint32_t*>(&t);
}
__device__ __forceinline__ int load_index(const void* p, long long i, int is64) {
    if (is64) return (int)((const long long*)p)[i];
    return ((const int*)p)[i];
}

// ---------- detect int width + zero accumulators ----------
__global__ void k_detect(const unsigned int* __restrict__ ei_words) {
    int t = threadIdx.x;
    if (t == 0) {
        unsigned int acc = 0;
#pragma unroll
        for (int i = 0; i < 64; i++) acc |= ei_words[2 * i + 1];
        g_idx64 = (acc == 0u) ? 1 : 0;
    }
    for (int i = t; i < NUM_GRAPHS * D_HID; i += 256) g_CR[i] = 0.f;
    if (t < NUM_GRAPHS) g_rowsum[t] = 0.f;
}

// ---------- batch -> uint8 + rowsum pw0 part (warp-aggregated histogram) ----------
__global__ void k_prep(const void* __restrict__ batch, const float* __restrict__ prop_w) {
    __shared__ float h[NUM_GRAPHS];
    int t = threadIdx.x;
    if (t < NUM_GRAPHS) h[t] = 0.f;
    __syncthreads();
    int is64 = g_idx64;
    float pw0 = prop_w[0];
    int i = blockIdx.x * blockDim.x + t;
    if (i < N_NODES) {
        int g = load_index(batch, i, is64) & (NUM_GRAPHS - 1);
        g_b8[i] = (unsigned char)g;
        // batch sorted -> nearly all lanes share g; aggregate per distinct value
        unsigned int mask = __match_any_sync(__activemask(), g);
        int leader = __ffs(mask) - 1;
        if ((t & 31) == leader) atomicAdd(&h[g], pw0 * (float)__popc(mask));
    }
    __syncthreads();
    if (t < NUM_GRAPHS && h[t] != 0.f) atomicAdd(&g_rowsum[t], h[t]);
}

// ---------- W1 -> pre-swizzled fp16 image ----------
__global__ void k_prepW(const float* __restrict__ w1) {
    int idx = blockIdx.x * blockDim.x + threadIdx.x;
    if (idx >= 2 * 128 * 128) return;
    int half = idx >> 14;
    int k = (idx >> 7) & 127;
    int n = idx & 127;
    float v = w1[(size_t)k * D_HID + half * 128 + n];
    uint32_t off = swz((uint32_t)k, (uint32_t)n * 2);
    *reinterpret_cast<__half*>(g_W1img + half * 32768 + off) = __float2half_rn(v);
}

// ---------- edge scatter into C + rowsum edge part ----------
__global__ void k_edges(const void* __restrict__ ei, const float* __restrict__ ew,
                        const float* __restrict__ prop_w) {
    __shared__ float h[NUM_GRAPHS];
    int t = threadIdx.x;
    if (t < NUM_GRAPHS) h[t] = 0.f;
    __syncthreads();
    float pw0 = prop_w[1], pw1 = prop_w[2], pw2 = prop_w[3];
    int is64 = g_idx64;
    const long long total = (long long)N_HOPS * N_EDGES;
    long long stride = (long long)gridDim.x * blockDim.x;
    for (long long idx = (long long)blockIdx.x * blockDim.x + t; idx < total;
         idx += stride) {
        int hop = (int)(idx / N_EDGES);
        long long r = idx - (long long)hop * N_EDGES;
        long long base = (long long)hop * 2 * N_EDGES;
        int s = load_index(ei, base + r, is64);
        int d = load_index(ei, base + N_EDGES + r, is64);
        s = min(max(s, 0), N_NODES - 1);
        d = min(max(d, 0), N_NODES - 1);
        float w = ew[(size_t)hop * N_EDGES + r];
        float pw = (hop == 0) ? pw0 : (hop == 1) ? pw1 : pw2;
        int g = g_b8[d];
        float val = pw * w;
        atomicAdd(&g_C[(size_t)s * NUM_GRAPHS + g], val);
        atomicAdd(&h[g], val);
    }
    __syncthreads();
    if (t < NUM_GRAPHS && h[t] != 0.f) atomicAdd(&g_rowsum[t], h[t]);
}

// ---------- fused: full-width GEMM1 (n=256) + GEMM2, 3 syncs/tile ----------
__global__ void __launch_bounds__(THREADS_F, 1)
k_fused(const float* __restrict__ x, const float* __restrict__ b1,
        const float* __restrict__ prop_w) {
    extern __shared__ char sm[];
    const uint32_t smb = smem_u32(sm);
    float* sb1 = reinterpret_cast<float*>(sm + OFF_B1);

    const int t = threadIdx.x;
    const int lane = t & 31;
    const int w = t >> 5;  // 0..15
    const float pw0 = prop_w[0];

    if (t < 256) sb1[t] = b1[t];
    {
        const uint4* src = reinterpret_cast<const uint4*>(g_W1img);
        uint4* dst = reinterpret_cast<uint4*>(sm + OFF_W);
#pragma unroll
        for (int i = 0; i < 8; i++) dst[t + i * THREADS_F] = src[t + i * THREADS_F];
    }

    const int m1base = (w & 3) * 32;
    const int hsel1 = w >> 3;
    const int n1base = ((w >> 2) & 1) * 64;
    const int m2base = (w & 3) * 16;
    const int hsel2 = w >> 3;
    const int n2base = ((w >> 2) & 1) * 64;

    const uint32_t lr = lane & 15;
    const uint32_t lc = (lane >> 4) * 16;
    const int qrow = lane >> 2;
    const int qcol = (lane & 3) * 2;

    float accG[8][4];
#pragma unroll
    for (int b = 0; b < 8; b++)
#pragma unroll
        for (int c = 0; c < 4; c++) accG[b][c] = 0.f;

    for (int tile = blockIdx.x; tile < NT_TILES; tile += gridDim.x) {
        __syncthreads();  // prev-tile readers of X/C/R done
        // ---- stage X tile -> fp16 swizzled ----
        {
            int row = t >> 2;
            int c0 = (t & 3) * 32;
            int node = tile * TM + row;
            bool valid = node < N_NODES;
            const float* xr = x + (size_t)node * D_FEAT + c0;
#pragma unroll
            for (int i = 0; i < 8; i++) {
                float4 f = valid ? *reinterpret_cast<const float4*>(xr + i * 4)
                                 : make_float4(0.f, 0.f, 0.f, 0.f);
                uint2 hv = make_uint2(pkhf2(f.x, f.y), pkhf2(f.z, f.w));
                uint32_t off = swz((uint32_t)row, (uint32_t)(c0 + i * 4) * 2);
                *reinterpret_cast<uint2*>(sm + OFF_X + off) = hv;
            }
        }
        // ---- stage C' (transposed fp16, pw0 folded) ----
        {
            int node = t >> 2;
            int g0 = (t & 3) * 16;
            int gn = tile * TM + node;
            bool valid = gn < N_NODES;
            int gb = valid ? (int)g_b8[gn] : -1;
            const float* cr = g_C + (size_t)gn * NUM_GRAPHS + g0;
#pragma unroll
            for (int i = 0; i < 4; i++) {
                float4 f = valid ? *reinterpret_cast<const float4*>(cr + i * 4)
                                 : make_float4(0.f, 0.f, 0.f, 0.f);
#pragma unroll
                for (int j = 0; j < 4; j++) {
                    int g = g0 + i * 4 + j;
                    float v = ((const float*)&f)[j];
                    if (g == gb) v += pw0;
                    uint32_t off = swz((uint32_t)g, (uint32_t)node * 2);
                    *reinterpret_cast<__half*>(sm + OFF_C + off) = __float2half_rn(v);
                }
            }
        }
        __syncthreads();

        // ---- GEMM1: acc1[m32][n64] = X @ W ----
        float acc1[2][8][4];
#pragma unroll
        for (int a = 0; a < 2; a++)
#pragma unroll
            for (int b = 0; b < 8; b++)
#pragma unroll
                for (int c = 0; c < 4; c++) acc1[a][b][c] = 0.f;
        {
            uint32_t Ab = smb + OFF_X;
            uint32_t Bb = smb + OFF_W + hsel1 * 32768;
#pragma unroll
            for (int k0 = 0; k0 < 128; k0 += 16) {
                uint32_t a[2][4], b[4][4];
#pragma unroll
                for (int mg = 0; mg < 2; mg++)
                    ldsm4(a[mg], Ab + swz(m1base + mg * 16 + lr, k0 * 2 + lc));
#pragma unroll
                for (int nt2 = 0; nt2 < 4; nt2++)
                    ldsm4t(b[nt2], Bb + swz(k0 + lr, (n1base + nt2 * 16) * 2 + lc));
#pragma unroll
                for (int mg = 0; mg < 2; mg++)
#pragma unroll
                    for (int nt = 0; nt < 8; nt++)
                        mma_fp16(acc1[mg][nt], a[mg], &b[nt >> 1][(nt & 1) * 2]);
            }
        }
        // ---- bias + relu -> R ----
        {
            char* Rimg = sm + OFF_R + hsel1 * 32768;
#pragma unroll
            for (int mg = 0; mg < 2; mg++) {
                int row0 = m1base + mg * 16 + qrow;
#pragma unroll
                for (int nt = 0; nt < 8; nt++) {
                    int col = n1base + nt * 8 + qcol;
                    float b0 = sb1[hsel1 * 128 + col];
                    float b1v = sb1[hsel1 * 128 + col + 1];
#pragma unroll
                    for (int rh = 0; rh < 2; rh++) {
                        float v0 = fmaxf(acc1[mg][nt][rh * 2 + 0] + b0, 0.f);
                        float v1 = fmaxf(acc1[mg][nt][rh * 2 + 1] + b1v, 0.f);
                        *reinterpret_cast<uint32_t*>(
                            Rimg + swz((uint32_t)(row0 + rh * 8), (uint32_t)col * 2)) =
                            pkhf2(v0, v1);
                    }
                }
            }
        }
        __syncthreads();  // R ready

        // ---- GEMM2: accG += C'[64 x 128nodes] @ R[128nodes x 256] ----
        {
            uint32_t Ab = smb + OFF_C;
            uint32_t Bb = smb + OFF_R + hsel2 * 32768;
#pragma unroll
            for (int k0 = 0; k0 < 128; k0 += 16) {
                uint32_t a[4], b[4][4];
                ldsm4(a, Ab + swz(m2base + lr, k0 * 2 + lc));
#pragma unroll
                for (int nt2 = 0; nt2 < 4; nt2++)
                    ldsm4t(b[nt2], Bb + swz(k0 + lr, (n2base + nt2 * 16) * 2 + lc));
#pragma unroll
                for (int nt = 0; nt < 8; nt++)
                    mma_fp16(accG[nt], a, &b[nt >> 1][(nt & 1) * 2]);
            }
        }
    }

    // ---- drain persistent accumulators ----
#pragma unroll
    for (int nt = 0; nt < 8; nt++) {
        int gr = m2base + qrow;
        int col = hsel2 * 128 + n2base + nt * 8 + qcol;
        atomicAdd(&g_CR[gr * D_HID + col], accG[nt][0]);
        atomicAdd(&g_CR[gr * D_HID + col + 1], accG[nt][1]);
        atomicAdd(&g_CR[(gr + 8) * D_HID + col], accG[nt][2]);
        atomicAdd(&g_CR[(gr + 8) * D_HID + col + 1], accG[nt][3]);
    }
}

// ---------- final: pooled = CR @ w2 + rowsum*b2, log_softmax ----------
__global__ void k_final(const float* __restrict__ w2, const float* __restrict__ b2,
                        float* __restrict__ out) {
    int g = blockIdx.x;
    int f = threadIdx.x;
    float v = g_rowsum[g] * b2[f];
    const float* cr = g_CR + g * D_HID;
#pragma unroll 8
    for (int k = 0; k < D_HID; k++) v += cr[k] * w2[k * D_FEAT + f];

    __shared__ float sh[D_FEAT];
    sh[f] = v;
    __syncthreads();
    for (int s = D_FEAT / 2; s > 0; s >>= 1) {
        if (f < s) sh[f] = fmaxf(sh[f], sh[f + s]);
        __syncthreads();
    }
    float m = sh[0];
    __syncthreads();
    sh[f] = expf(v - m);
    __syncthreads();
    for (int s = D_FEAT / 2; s > 0; s >>= 1) {
        if (f < s) sh[f] += sh[f + s];
        __syncthreads();
    }
    float lse = logf(sh[0]);
    out[g * D_FEAT + f] = v - m - lse;
}

extern "C" void kernel_launch(void* const* d_in, const int* in_sizes, int n_in,
                              void* d_out, int out_size) {
    const float* x = (const float*)d_in[0];
    const void* ei = d_in[1];
    const float* ew = (const float*)d_in[2];
    const void* batch = d_in[3];
    const float* w1 = (const float*)d_in[4];
    const float* b1 = (const float*)d_in[5];
    const float* w2 = (const float*)d_in[6];
    const float* b2 = (const float*)d_in[7];
    const float* pw = (const float*)d_in[8];
    float* out = (float*)d_out;

    cudaFuncSetAttribute(k_fused, cudaFuncAttributeMaxDynamicSharedMemorySize, SMEM_F);

    k_detect<<<1, 256>>>((const unsigned int*)ei);
    k_prep<<<(N_NODES + 255) / 256, 256>>>(batch, pw);
    k_prepW<<<128, 256>>>(w1);
    // zero C via async memset (graph-capturable, no allocation)
    void* cPtr = nullptr;
    cudaGetSymbolAddress(&cPtr, g_C);
    cudaMemsetAsync(cPtr, 0, (size_t)N_NODES * NUM_GRAPHS * sizeof(float), 0);
    k_edges<<<4096, 256>>>(ei, ew, pw);
    k_fused<<<GRID_F, THREADS_F, SMEM_F>>>(x, b1, pw);
    k_final<<<NUM_GRAPHS, D_FEAT>>>(w2, b2, out);
}